// round 1
// baseline (speedup 1.0000x reference)
#include <cuda_runtime.h>
#include <math.h>

#define NN    100000
#define NE    1600000
#define NG    512
#define HID   200
#define H3    600
#define INDIM 205

// ---------------- scratch (device globals; no runtime alloc) ----------------
__device__ float g_h  [(size_t)NN * HID];
__device__ float g_m  [(size_t)NN * HID];
__device__ float g_agg[(size_t)NN * HID];
__device__ float g_gi [(size_t)NN * H3];
__device__ float g_gh [(size_t)NN * H3];
__device__ float g_pool[NG * 2 * HID];   // [g][0..199]=mean-sum, [g][200..399]=max
__device__ float g_cnt [NG];
__device__ float g_fc1 [NG * HID];
__device__ float g_scale[3 * HID];       // 0=bn1, 1=bn2, 2=bnf
__device__ float g_shift[3 * HID];
__device__ int   g_src[NE];
__device__ int   g_dst[NE];
__device__ int   g_batch[NN];
__device__ int   g_flag_e;               // 1 => int64 input
__device__ int   g_flag_b;

// ---------------- dtype detection (int64 vs int32) ----------------
// If int64: odd 32-bit words are high halves of small nonneg values -> all 0.
// Windows chosen near the END of the int32 interpretation so nonzero values
// are guaranteed there in the int32 case (batch is sorted ascending).
__global__ void k_detect(const int* __restrict__ ew, const int* __restrict__ bw) {
    if (blockIdx.x == 0 && threadIdx.x == 0) {
        int fe = 1;
        for (int w = 2 * NE - 255; w < 2 * NE; w += 2)
            if (ew[w] != 0) fe = 0;
        g_flag_e = fe;
        int fb = 1;
        for (int w = NN - 255; w < NN; w += 2)
            if (bw[w] != 0) fb = 0;
        g_flag_b = fb;
    }
}

__global__ void k_conv_edges(const void* __restrict__ e) {
    int i = blockIdx.x * blockDim.x + threadIdx.x;
    if (i >= 2 * NE) return;
    int v = g_flag_e ? (int)((const long long*)e)[i] : ((const int*)e)[i];
    if (i < NE) g_src[i] = v; else g_dst[i - NE] = v;
}

__global__ void k_conv_batch(const void* __restrict__ b) {
    int i = blockIdx.x * blockDim.x + threadIdx.x;
    if (i >= NN) return;
    g_batch[i] = g_flag_b ? (int)((const long long*)b)[i] : ((const int*)b)[i];
}

// ---------------- BN param prep: scale=g*rsqrt(v+eps), shift=b-m*scale ------
__global__ void k_bnprep(const float* __restrict__ g, const float* __restrict__ b,
                         const float* __restrict__ m, const float* __restrict__ v,
                         int which) {
    int j = threadIdx.x;
    if (j < HID) {
        float s = g[j] * rsqrtf(v[j] + 1e-5f);
        g_scale[which * HID + j] = s;
        g_shift[which * HID + j] = b[j] - m[j] * s;
    }
}

// ---------------- generic fp32 GEMM: C = A[M,K] @ op(B) (+bias,bn,relu) -----
// transB==0: B is [K,N] row-major.  transB==1: B is [N,K] row-major.
#define BM 64
#define BN 64
#define BK 16

__global__ void k_gemm(const float* __restrict__ A, const float* __restrict__ B,
                       float* __restrict__ C, int M, int N, int K, int transB,
                       const float* __restrict__ bias,
                       const float* __restrict__ scale,
                       const float* __restrict__ shift, int relu) {
    __shared__ float As[BK][BM];
    __shared__ float Bs[BK][BN + 4];

    const int m0 = blockIdx.y * BM;
    const int n0 = blockIdx.x * BN;
    const int tid = threadIdx.x;
    const int tm = tid >> 4;   // 0..15
    const int tn = tid & 15;   // 0..15

    float acc[4][4];
#pragma unroll
    for (int i = 0; i < 4; i++)
#pragma unroll
        for (int j = 0; j < 4; j++) acc[i][j] = 0.f;

    for (int k0 = 0; k0 < K; k0 += BK) {
        // A tile: thread loads 4 consecutive-k scalars
        {
            int ar = tid >> 2;          // m offset 0..63
            int ac = (tid & 3) * 4;     // k offset 0,4,8,12
            int m = m0 + ar;
#pragma unroll
            for (int i = 0; i < 4; i++) {
                int k = k0 + ac + i;
                As[ac + i][ar] = (m < M && k < K) ? A[(size_t)m * K + k] : 0.f;
            }
        }
        if (!transB) {
            int br = tid >> 4;          // k offset 0..15
            int bc = (tid & 15) * 4;    // n offset
            int k = k0 + br;
#pragma unroll
            for (int i = 0; i < 4; i++) {
                int n = n0 + bc + i;
                Bs[br][bc + i] = (k < K && n < N) ? B[(size_t)k * N + n] : 0.f;
            }
        } else {
            int br = tid >> 2;          // n offset 0..63
            int bc = (tid & 3) * 4;     // k offset
            int n = n0 + br;
#pragma unroll
            for (int i = 0; i < 4; i++) {
                int k = k0 + bc + i;
                Bs[bc + i][br] = (n < N && k < K) ? B[(size_t)n * K + k] : 0.f;
            }
        }
        __syncthreads();

#pragma unroll
        for (int k = 0; k < BK; k++) {
            float a[4], b[4];
#pragma unroll
            for (int i = 0; i < 4; i++) a[i] = As[k][tm * 4 + i];
#pragma unroll
            for (int j = 0; j < 4; j++) b[j] = Bs[k][tn * 4 + j];
#pragma unroll
            for (int i = 0; i < 4; i++)
#pragma unroll
                for (int j = 0; j < 4; j++) acc[i][j] += a[i] * b[j];
        }
        __syncthreads();
    }

#pragma unroll
    for (int i = 0; i < 4; i++) {
        int m = m0 + tm * 4 + i;
        if (m >= M) continue;
#pragma unroll
        for (int j = 0; j < 4; j++) {
            int n = n0 + tn * 4 + j;
            if (n >= N) continue;
            float v = acc[i][j];
            if (bias)  v += bias[n];
            if (scale) v = v * scale[n] + shift[n];
            if (relu)  v = fmaxf(v, 0.f);
            C[(size_t)m * N + n] = v;
        }
    }
}

// ---------------- zero helper ----------------
__global__ void k_zero(float* __restrict__ p, int n) {
    int i = blockIdx.x * blockDim.x + threadIdx.x;
    if (i < n) p[i] = 0.f;
}

// ---------------- edge scatter-add: agg[dst] += m[src] (vec4 red) -----------
__global__ void k_scatter() {
    int t = blockIdx.x * blockDim.x + threadIdx.x;
    if (t >= NE * 50) return;
    int e = t / 50;
    int c = t - e * 50;
    int s = g_src[e];
    int d = g_dst[e];
    const float4 v = *reinterpret_cast<const float4*>(&g_m[(size_t)s * HID + c * 4]);
    float* p = &g_agg[(size_t)d * HID + c * 4];
    asm volatile("red.global.add.v4.f32 [%0], {%1,%2,%3,%4};"
                 :: "l"(p), "f"(v.x), "f"(v.y), "f"(v.z), "f"(v.w) : "memory");
}

// ---------------- GRU cell elementwise (in-place h update) ------------------
__global__ void k_gru() {
    int idx = blockIdx.x * blockDim.x + threadIdx.x;
    if (idx >= NN * HID) return;
    int n = idx / HID;
    int j = idx - n * HID;
    const float* gi = &g_gi[(size_t)n * H3];
    const float* gh = &g_gh[(size_t)n * H3];
    float ir = gi[j], iz = gi[j + HID], in = gi[j + 2 * HID];
    float hr = gh[j], hz = gh[j + HID], hn = gh[j + 2 * HID];
    float r = 1.f / (1.f + expf(-(ir + hr)));
    float z = 1.f / (1.f + expf(-(iz + hz)));
    float nn = tanhf(in + r * hn);
    g_h[idx] = (1.f - z) * nn + z * g_h[idx];
}

// ---------------- bn2 + relu, in place on h ---------------------------------
__global__ void k_bn2relu() {
    int idx = blockIdx.x * blockDim.x + threadIdx.x;
    if (idx >= NN * HID) return;
    int j = idx % HID;
    g_h[idx] = fmaxf(g_h[idx] * g_scale[HID + j] + g_shift[HID + j], 0.f);
}

// ---------------- per-graph pooling (mean-sum + max; h >= 0 post relu) ------
__global__ void k_pool() {
    int t = blockIdx.x * blockDim.x + threadIdx.x;
    if (t >= NN * 50) return;
    int node = t / 50;
    int c = t - node * 50;
    int b = g_batch[node];
    const float4 v = *reinterpret_cast<const float4*>(&g_h[(size_t)node * HID + c * 4]);
    float* mp = &g_pool[b * 400 + c * 4];
    atomicAdd(mp + 0, v.x); atomicAdd(mp + 1, v.y);
    atomicAdd(mp + 2, v.z); atomicAdd(mp + 3, v.w);
    // values are >= 0, so int-compare atomicMax is order-preserving
    int* xp = (int*)&g_pool[b * 400 + 200 + c * 4];
    atomicMax(xp + 0, __float_as_int(v.x));
    atomicMax(xp + 1, __float_as_int(v.y));
    atomicMax(xp + 2, __float_as_int(v.z));
    atomicMax(xp + 3, __float_as_int(v.w));
    if (c == 0) atomicAdd(&g_cnt[b], 1.0f);
}

__global__ void k_pool_fin() {
    int idx = blockIdx.x * blockDim.x + threadIdx.x;
    if (idx >= NG * HID) return;
    int g = idx / HID;
    int j = idx - g * HID;
    g_pool[g * 400 + j] *= 1.f / fmaxf(g_cnt[g], 1.f);
}

// ---------------- host launch ----------------
static inline int cdiv(int a, int b) { return (a + b - 1) / b; }

extern "C" void kernel_launch(void* const* d_in, const int* in_sizes, int n_in,
                              void* d_out, int out_size) {
    // resolve scratch symbol addresses once (identical work every call)
    static bool init = false;
    static float *p_h, *p_m, *p_agg, *p_gi, *p_gh, *p_pool, *p_cnt, *p_fc1, *p_scale, *p_shift;
    if (!init) {
        cudaGetSymbolAddress((void**)&p_h, g_h);
        cudaGetSymbolAddress((void**)&p_m, g_m);
        cudaGetSymbolAddress((void**)&p_agg, g_agg);
        cudaGetSymbolAddress((void**)&p_gi, g_gi);
        cudaGetSymbolAddress((void**)&p_gh, g_gh);
        cudaGetSymbolAddress((void**)&p_pool, g_pool);
        cudaGetSymbolAddress((void**)&p_cnt, g_cnt);
        cudaGetSymbolAddress((void**)&p_fc1, g_fc1);
        cudaGetSymbolAddress((void**)&p_scale, g_scale);
        cudaGetSymbolAddress((void**)&p_shift, g_shift);
        init = true;
    }

    // ---- input mapping: disambiguate metadata order at runtime ----
    const float *x, *projW, *projb;
    const void  *edge, *batch;
    const float *bn1g, *bn1b, *bn1m, *bn1v;
    const float *bn2g, *bn2b, *bn2m, *bn2v;
    const float *bnfg, *bnfb, *bnfm, *bnfv;
    const float *ggcW, *wih, *whh, *bih, *bhh, *fc1W, *fc1b, *fc2W, *fc2b;

    x     = (const float*)d_in[0];
    edge  = d_in[1];
    batch = d_in[2];
    projW = (const float*)d_in[3];
    projb = (const float*)d_in[4];
    bn1g = (const float*)d_in[5]; bn1b = (const float*)d_in[6];
    bn1m = (const float*)d_in[7]; bn1v = (const float*)d_in[8];

    if (in_sizes[9] == 120000) {
        // reference-signature order
        ggcW = (const float*)d_in[9];
        wih  = (const float*)d_in[10]; whh = (const float*)d_in[11];
        bih  = (const float*)d_in[12]; bhh = (const float*)d_in[13];
        bn2g = (const float*)d_in[14]; bn2b = (const float*)d_in[15];
        bn2m = (const float*)d_in[16]; bn2v = (const float*)d_in[17];
        fc1W = (const float*)d_in[18]; fc1b = (const float*)d_in[19];
        bnfg = (const float*)d_in[20]; bnfb = (const float*)d_in[21];
        bnfm = (const float*)d_in[22]; bnfv = (const float*)d_in[23];
        fc2W = (const float*)d_in[24]; fc2b = (const float*)d_in[25];
    } else {
        // setup_inputs dict order
        bn2g = (const float*)d_in[9];  bn2b = (const float*)d_in[10];
        bn2m = (const float*)d_in[11]; bn2v = (const float*)d_in[12];
        bnfg = (const float*)d_in[13]; bnfb = (const float*)d_in[14];
        bnfm = (const float*)d_in[15]; bnfv = (const float*)d_in[16];
        ggcW = (const float*)d_in[17];
        wih  = (const float*)d_in[18]; whh = (const float*)d_in[19];
        bih  = (const float*)d_in[20]; bhh = (const float*)d_in[21];
        fc1W = (const float*)d_in[22]; fc1b = (const float*)d_in[23];
        fc2W = (const float*)d_in[24]; fc2b = (const float*)d_in[25];
    }

    const int T = 256;

    // dtype detection + index normalization
    k_detect<<<1, 32>>>((const int*)edge, (const int*)batch);
    k_conv_edges<<<cdiv(2 * NE, T), T>>>(edge);
    k_conv_batch<<<cdiv(NN, T), T>>>(batch);

    // BN param prep
    k_bnprep<<<1, 256>>>(bn1g, bn1b, bn1m, bn1v, 0);
    k_bnprep<<<1, 256>>>(bn2g, bn2b, bn2m, bn2v, 1);
    k_bnprep<<<1, 256>>>(bnfg, bnfb, bnfm, bnfv, 2);

    // h = relu(bn1(x @ projW^T + projb))
    {
        dim3 grid(cdiv(HID, BN), cdiv(NN, BM));
        k_gemm<<<grid, T>>>(x, projW, p_h, NN, HID, INDIM, 1,
                            projb, p_scale + 0, p_shift + 0, 1);
    }

    // 3 GatedGraphConv steps
    for (int it = 0; it < 3; it++) {
        dim3 gridH(cdiv(HID, BN), cdiv(NN, BM));
        // m = h @ ggc_W[it]
        k_gemm<<<gridH, T>>>(p_h, ggcW + (size_t)it * HID * HID, p_m,
                             NN, HID, HID, 0, nullptr, nullptr, nullptr, 0);
        // agg = scatter_add(m[src] -> dst)
        k_zero<<<cdiv(NN * HID, T), T>>>(p_agg, NN * HID);
        k_scatter<<<cdiv(NE * 50, T), T>>>();
        // gi = agg @ wih^T + bih ; gh = h @ whh^T + bhh
        dim3 grid3(cdiv(H3, BN), cdiv(NN, BM));
        k_gemm<<<grid3, T>>>(p_agg, wih, p_gi, NN, H3, HID, 1,
                             bih, nullptr, nullptr, 0);
        k_gemm<<<grid3, T>>>(p_h, whh, p_gh, NN, H3, HID, 1,
                             bhh, nullptr, nullptr, 0);
        // h = GRU(agg-gates, h-gates, h)
        k_gru<<<cdiv(NN * HID, T), T>>>();
    }

    // bn2 + relu (in place)
    k_bn2relu<<<cdiv(NN * HID, T), T>>>();

    // pooling
    k_zero<<<cdiv(NG * 400, T), T>>>(p_pool, NG * 400);
    k_zero<<<cdiv(NG, T), T>>>(p_cnt, NG);
    k_pool<<<cdiv(NN * 50, T), T>>>();
    k_pool_fin<<<cdiv(NG * HID, T), T>>>();

    // fc1 + bnf + relu : [512,200] = pool[512,400] @ fc1_W^T
    {
        dim3 grid(cdiv(HID, BN), cdiv(NG, BM));
        k_gemm<<<grid, T>>>(p_pool, fc1W, p_fc1, NG, HID, 2 * HID, 1,
                            fc1b, p_scale + 2 * HID, p_shift + 2 * HID, 1);
    }
    // fc2 : [512,2]
    {
        dim3 grid(cdiv(2, BN), cdiv(NG, BM));
        k_gemm<<<grid, T>>>(p_fc1, fc2W, (float*)d_out, NG, 2, HID, 1,
                            fc2b, nullptr, nullptr, 0);
    }
}

// round 4
// speedup vs baseline: 1.6710x; 1.6710x over previous
#include <cuda_runtime.h>
#include <cuda_bf16.h>
#include <stdint.h>
#include <math.h>

#define NN    100000
#define NE    1600000
#define NG    512
#define HID   200
#define H3    600
#define INDIM 205

#define KP    208      // padded K per section
#define K3    624      // 3*KP
#define NCH   78       // K3/8 chunks
#define NSTEP 39       // K3/16

// ---------------- scratch (device globals; no runtime alloc) ----------------
__device__ float g_h  [(size_t)NN * HID];
__device__ float g_m  [(size_t)NN * HID];
__device__ float g_agg[(size_t)NN * HID];
__device__ float g_gi [(size_t)NN * H3];
__device__ float g_gh [(size_t)NN * H3];
__device__ float g_pool[NG * 2 * HID];
__device__ float g_cnt [NG];
__device__ float g_fc1 [NG * HID];
__device__ float g_scale[3 * HID];
__device__ float g_shift[3 * HID];
__device__ int   g_src[NE];
__device__ int   g_dst[NE];
__device__ int   g_batch[NN];
__device__ int   g_flag_e;
__device__ int   g_flag_b;

// bf16 split buffers
__device__ __nv_bfloat16 g_xs[(size_t)NN * K3];
__device__ __nv_bfloat16 g_hs[(size_t)NN * K3];
__device__ __nv_bfloat16 g_as[(size_t)NN * K3];
__device__ __nv_bfloat16 g_Bproj[256 * K3];
__device__ __nv_bfloat16 g_Bggc [3][256 * K3];
__device__ __nv_bfloat16 g_Bwih [640 * K3];
__device__ __nv_bfloat16 g_Bwhh [640 * K3];

// ---------------- dtype detection (int64 vs int32) ----------------
__global__ void k_detect(const int* __restrict__ ew, const int* __restrict__ bw) {
    if (blockIdx.x == 0 && threadIdx.x == 0) {
        int fe = 1;
        for (int w = 2 * NE - 255; w < 2 * NE; w += 2)
            if (ew[w] != 0) fe = 0;
        g_flag_e = fe;
        int fb = 1;
        for (int w = NN - 255; w < NN; w += 2)
            if (bw[w] != 0) fb = 0;
        g_flag_b = fb;
    }
}

__global__ void k_conv_edges(const void* __restrict__ e) {
    int i = blockIdx.x * blockDim.x + threadIdx.x;
    if (i >= 2 * NE) return;
    int v = g_flag_e ? (int)((const long long*)e)[i] : ((const int*)e)[i];
    if (i < NE) g_src[i] = v; else g_dst[i - NE] = v;
}

__global__ void k_conv_batch(const void* __restrict__ b) {
    int i = blockIdx.x * blockDim.x + threadIdx.x;
    if (i >= NN) return;
    g_batch[i] = g_flag_b ? (int)((const long long*)b)[i] : ((const int*)b)[i];
}

// ---------------- BN param prep ----------------
__global__ void k_bnprep(const float* __restrict__ g, const float* __restrict__ b,
                         const float* __restrict__ m, const float* __restrict__ v,
                         int which) {
    int j = threadIdx.x;
    if (j < HID) {
        float s = g[j] * rsqrtf(v[j] + 1e-5f);
        g_scale[which * HID + j] = s;
        g_shift[which * HID + j] = b[j] - m[j] * s;
    }
}

// ---------------- bf16 split of activations: [M,K] f32 -> [M,624] bf16 ------
// layout per row: [hi(0..207) | lo(0..207) | hi(0..207)], zeros for k >= K
__global__ void k_splitA(const float* __restrict__ in, __nv_bfloat16* __restrict__ out,
                         int K) {
    int idx = blockIdx.x * blockDim.x + threadIdx.x;
    if (idx >= NN * NCH) return;
    int m = idx / NCH, ch = idx - (idx / NCH) * NCH;
    int s = ch / 26;
    int k0 = (ch - s * 26) * 8;
    const float* src = in + (size_t)m * K + k0;
    __nv_bfloat16 o[8];
#pragma unroll
    for (int i = 0; i < 8; i++) {
        float v = (k0 + i < K) ? src[i] : 0.f;
        __nv_bfloat16 hi = __float2bfloat16(v);
        o[i] = (s == 1) ? __float2bfloat16(v - __bfloat162float(hi)) : hi;
    }
    *(uint4*)(out + (size_t)m * K3 + ch * 8) = *(const uint4*)o;
}

// ---------------- bf16 split of weights: logical B[K,N] -> out[Npad,624] ----
// out[n][s*208+k]: s0=hi, s1=hi, s2=lo.  trans=1: W is [N,K] row-major.
__global__ void k_splitB(const float* __restrict__ W, __nv_bfloat16* __restrict__ out,
                         int N, int Npad, int K, int trans) {
    int idx = blockIdx.x * blockDim.x + threadIdx.x;
    if (idx >= Npad * NCH) return;
    int n = idx / NCH, ch = idx - (idx / NCH) * NCH;
    int s = ch / 26;
    int k0 = (ch - s * 26) * 8;
    __nv_bfloat16 o[8];
#pragma unroll
    for (int i = 0; i < 8; i++) {
        int k = k0 + i;
        float v = 0.f;
        if (n < N && k < K) v = trans ? W[(size_t)n * K + k] : W[(size_t)k * N + n];
        __nv_bfloat16 hi = __float2bfloat16(v);
        o[i] = (s == 2) ? __float2bfloat16(v - __bfloat162float(hi)) : hi;
    }
    *(uint4*)(out + (size_t)n * K3 + ch * 8) = *(const uint4*)o;
}

// ---------------- tensor-core GEMM: C[M,N] = A'[M,624] @ B'[Npad,624]^T -----
// 128x64 CTA tile, 8 warps (4x2), warp tile 32x32, mma.m16n8k16.bf16
#define SA_STRIDE 24
#define SB_STRIDE 24

__global__ void __launch_bounds__(256)
k_tgemm(const __nv_bfloat16* __restrict__ A, const __nv_bfloat16* __restrict__ B,
        float* __restrict__ C, int M, int N,
        const float* __restrict__ bias,
        const float* __restrict__ scale, const float* __restrict__ shift,
        int relu) {
    __shared__ __nv_bfloat16 sA[2][128 * SA_STRIDE];
    __shared__ __nv_bfloat16 sB[2][64 * SB_STRIDE];

    const int tid  = threadIdx.x;
    const int warp = tid >> 5, lane = tid & 31;
    const int wm = warp & 3, wn = warp >> 2;
    const int m0 = blockIdx.y * 128;
    const int n0 = blockIdx.x * 64;

    const int arow = tid >> 1;
    const int akc  = (tid & 1) * 8;

    float acc[2][4][4];
#pragma unroll
    for (int mi = 0; mi < 2; mi++)
#pragma unroll
        for (int ni = 0; ni < 4; ni++)
#pragma unroll
            for (int j = 0; j < 4; j++) acc[mi][ni][j] = 0.f;

    const size_t a_off = (size_t)(m0 + arow) * K3 + akc;
    const size_t b_off = (size_t)(n0 + arow) * K3 + akc;   // only tid<128 uses (arow<64)
    const int a_valid = (m0 + arow < M) ? 16 : 0;

    // prologue: stage 0
    {
        uint32_t d = (uint32_t)__cvta_generic_to_shared(&sA[0][arow * SA_STRIDE + akc]);
        asm volatile("cp.async.cg.shared.global [%0], [%1], 16, %2;\n"
                     :: "r"(d), "l"(A + a_off), "r"(a_valid));
        if (tid < 128) {
            uint32_t db = (uint32_t)__cvta_generic_to_shared(&sB[0][arow * SB_STRIDE + akc]);
            asm volatile("cp.async.cg.shared.global [%0], [%1], 16, 16;\n"
                         :: "r"(db), "l"(B + b_off));
        }
        asm volatile("cp.async.commit_group;\n");
    }

    const int lr = lane & 15;
    const int lcb = (lane >> 4) * 8;
    const int bn = lane >> 2;
    const int bk = (lane & 3) * 2;

    for (int ks = 0; ks < NSTEP; ks++) {
        // issue next stage
        if (ks + 1 < NSTEP) {
            int buf = (ks + 1) & 1;
            uint32_t d = (uint32_t)__cvta_generic_to_shared(&sA[buf][arow * SA_STRIDE + akc]);
            asm volatile("cp.async.cg.shared.global [%0], [%1], 16, %2;\n"
                         :: "r"(d), "l"(A + a_off + (ks + 1) * 16), "r"(a_valid));
            if (tid < 128) {
                uint32_t db = (uint32_t)__cvta_generic_to_shared(&sB[buf][arow * SB_STRIDE + akc]);
                asm volatile("cp.async.cg.shared.global [%0], [%1], 16, 16;\n"
                             :: "r"(db), "l"(B + b_off + (ks + 1) * 16));
            }
        }
        asm volatile("cp.async.commit_group;\n");
        asm volatile("cp.async.wait_group 1;\n");
        __syncthreads();

        const int buf = ks & 1;
        uint32_t a[2][4];
        uint32_t b[4][2];
#pragma unroll
        for (int mi = 0; mi < 2; mi++) {
            uint32_t addr = (uint32_t)__cvta_generic_to_shared(
                &sA[buf][(wm * 32 + mi * 16 + lr) * SA_STRIDE + lcb]);
            asm volatile("ldmatrix.sync.aligned.m8n8.x4.shared.b16 {%0,%1,%2,%3}, [%4];"
                         : "=r"(a[mi][0]), "=r"(a[mi][1]), "=r"(a[mi][2]), "=r"(a[mi][3])
                         : "r"(addr));
        }
#pragma unroll
        for (int ni = 0; ni < 4; ni++) {
            const __nv_bfloat16* p = &sB[buf][(wn * 32 + ni * 8 + bn) * SB_STRIDE + bk];
            b[ni][0] = *(const uint32_t*)p;
            b[ni][1] = *(const uint32_t*)(p + 8);
        }
#pragma unroll
        for (int mi = 0; mi < 2; mi++)
#pragma unroll
            for (int ni = 0; ni < 4; ni++) {
                asm volatile(
                    "mma.sync.aligned.m16n8k16.row.col.f32.bf16.bf16.f32 "
                    "{%0,%1,%2,%3}, {%4,%5,%6,%7}, {%8,%9}, {%0,%1,%2,%3};"
                    : "+f"(acc[mi][ni][0]), "+f"(acc[mi][ni][1]),
                      "+f"(acc[mi][ni][2]), "+f"(acc[mi][ni][3])
                    : "r"(a[mi][0]), "r"(a[mi][1]), "r"(a[mi][2]), "r"(a[mi][3]),
                      "r"(b[ni][0]), "r"(b[ni][1]));
            }
        __syncthreads();
    }

    // epilogue
    const int r = lane >> 2;
    const int c = (lane & 3) * 2;
#pragma unroll
    for (int mi = 0; mi < 2; mi++) {
#pragma unroll
        for (int ni = 0; ni < 4; ni++) {
            int n = n0 + wn * 32 + ni * 8 + c;
            if (n >= N) continue;
            float bia0 = 0.f, bia1 = 0.f, sc0 = 1.f, sc1 = 1.f, sh0 = 0.f, sh1 = 0.f;
            bool n1ok = (n + 1 < N);
            if (bias)  { bia0 = bias[n]; if (n1ok) bia1 = bias[n + 1]; }
            if (scale) { sc0 = scale[n]; sh0 = shift[n];
                         if (n1ok) { sc1 = scale[n + 1]; sh1 = shift[n + 1]; } }
#pragma unroll
            for (int half = 0; half < 2; half++) {
                int m = m0 + wm * 32 + mi * 16 + half * 8 + r;
                if (m >= M) continue;
                float v0 = acc[mi][ni][half * 2 + 0] + bia0;
                float v1 = acc[mi][ni][half * 2 + 1] + bia1;
                if (scale) { v0 = v0 * sc0 + sh0; v1 = v1 * sc1 + sh1; }
                if (relu)  { v0 = fmaxf(v0, 0.f); v1 = fmaxf(v1, 0.f); }
                float* p = C + (size_t)m * N + n;
                p[0] = v0;
                if (n1ok) p[1] = v1;
            }
        }
    }
}

// ---------------- small SIMT GEMM (kept for fc1/fc2) ------------------------
#define BM 64
#define BN 64
#define BK 16
__global__ void k_gemm(const float* __restrict__ A, const float* __restrict__ B,
                       float* __restrict__ C, int M, int N, int K, int transB,
                       const float* __restrict__ bias,
                       const float* __restrict__ scale,
                       const float* __restrict__ shift, int relu) {
    __shared__ float As[BK][BM];
    __shared__ float Bs[BK][BN + 4];
    const int m0 = blockIdx.y * BM;
    const int n0 = blockIdx.x * BN;
    const int tid = threadIdx.x;
    const int tm = tid >> 4;
    const int tn = tid & 15;
    float acc[4][4];
#pragma unroll
    for (int i = 0; i < 4; i++)
#pragma unroll
        for (int j = 0; j < 4; j++) acc[i][j] = 0.f;

    for (int k0 = 0; k0 < K; k0 += BK) {
        {
            int ar = tid >> 2;
            int ac = (tid & 3) * 4;
            int m = m0 + ar;
#pragma unroll
            for (int i = 0; i < 4; i++) {
                int k = k0 + ac + i;
                As[ac + i][ar] = (m < M && k < K) ? A[(size_t)m * K + k] : 0.f;
            }
        }
        if (!transB) {
            int br = tid >> 4;
            int bc = (tid & 15) * 4;
            int k = k0 + br;
#pragma unroll
            for (int i = 0; i < 4; i++) {
                int n = n0 + bc + i;
                Bs[br][bc + i] = (k < K && n < N) ? B[(size_t)k * N + n] : 0.f;
            }
        } else {
            int br = tid >> 2;
            int bc = (tid & 3) * 4;
            int n = n0 + br;
#pragma unroll
            for (int i = 0; i < 4; i++) {
                int k = k0 + bc + i;
                Bs[bc + i][br] = (n < N && k < K) ? B[(size_t)n * K + k] : 0.f;
            }
        }
        __syncthreads();
#pragma unroll
        for (int k = 0; k < BK; k++) {
            float a[4], b[4];
#pragma unroll
            for (int i = 0; i < 4; i++) a[i] = As[k][tm * 4 + i];
#pragma unroll
            for (int j = 0; j < 4; j++) b[j] = Bs[k][tn * 4 + j];
#pragma unroll
            for (int i = 0; i < 4; i++)
#pragma unroll
                for (int j = 0; j < 4; j++) acc[i][j] += a[i] * b[j];
        }
        __syncthreads();
    }
#pragma unroll
    for (int i = 0; i < 4; i++) {
        int m = m0 + tm * 4 + i;
        if (m >= M) continue;
#pragma unroll
        for (int j = 0; j < 4; j++) {
            int n = n0 + tn * 4 + j;
            if (n >= N) continue;
            float v = acc[i][j];
            if (bias)  v += bias[n];
            if (scale) v = v * scale[n] + shift[n];
            if (relu)  v = fmaxf(v, 0.f);
            C[(size_t)m * N + n] = v;
        }
    }
}

// ---------------- zero helper ----------------
__global__ void k_zero(float* __restrict__ p, int n) {
    int i = blockIdx.x * blockDim.x + threadIdx.x;
    if (i < n) p[i] = 0.f;
}

// ---------------- edge scatter-add ----------------
__global__ void k_scatter() {
    int t = blockIdx.x * blockDim.x + threadIdx.x;
    if (t >= NE * 50) return;
    int e = t / 50;
    int c = t - e * 50;
    int s = g_src[e];
    int d = g_dst[e];
    const float4 v = *reinterpret_cast<const float4*>(&g_m[(size_t)s * HID + c * 4]);
    float* p = &g_agg[(size_t)d * HID + c * 4];
    asm volatile("red.global.add.v4.f32 [%0], {%1,%2,%3,%4};"
                 :: "l"(p), "f"(v.x), "f"(v.y), "f"(v.z), "f"(v.w) : "memory");
}

// ---------------- GRU cell elementwise ----------------
__global__ void k_gru() {
    int idx = blockIdx.x * blockDim.x + threadIdx.x;
    if (idx >= NN * HID) return;
    int n = idx / HID;
    int j = idx - n * HID;
    const float* gi = &g_gi[(size_t)n * H3];
    const float* gh = &g_gh[(size_t)n * H3];
    float ir = gi[j], iz = gi[j + HID], in = gi[j + 2 * HID];
    float hr = gh[j], hz = gh[j + HID], hn = gh[j + 2 * HID];
    float r = 1.f / (1.f + expf(-(ir + hr)));
    float z = 1.f / (1.f + expf(-(iz + hz)));
    float nn = tanhf(in + r * hn);
    g_h[idx] = (1.f - z) * nn + z * g_h[idx];
}

__global__ void k_bn2relu() {
    int idx = blockIdx.x * blockDim.x + threadIdx.x;
    if (idx >= NN * HID) return;
    int j = idx % HID;
    g_h[idx] = fmaxf(g_h[idx] * g_scale[HID + j] + g_shift[HID + j], 0.f);
}

// ---------------- pooling ----------------
__global__ void k_pool() {
    int t = blockIdx.x * blockDim.x + threadIdx.x;
    if (t >= NN * 50) return;
    int node = t / 50;
    int c = t - node * 50;
    int b = g_batch[node];
    const float4 v = *reinterpret_cast<const float4*>(&g_h[(size_t)node * HID + c * 4]);
    float* mp = &g_pool[b * 400 + c * 4];
    atomicAdd(mp + 0, v.x); atomicAdd(mp + 1, v.y);
    atomicAdd(mp + 2, v.z); atomicAdd(mp + 3, v.w);
    int* xp = (int*)&g_pool[b * 400 + 200 + c * 4];
    atomicMax(xp + 0, __float_as_int(v.x));
    atomicMax(xp + 1, __float_as_int(v.y));
    atomicMax(xp + 2, __float_as_int(v.z));
    atomicMax(xp + 3, __float_as_int(v.w));
    if (c == 0) atomicAdd(&g_cnt[b], 1.0f);
}

__global__ void k_pool_fin() {
    int idx = blockIdx.x * blockDim.x + threadIdx.x;
    if (idx >= NG * HID) return;
    int g = idx / HID;
    int j = idx - g * HID;
    g_pool[g * 400 + j] *= 1.f / fmaxf(g_cnt[g], 1.f);
}

// ---------------- host launch ----------------
static inline int cdiv(int a, int b) { return (a + b - 1) / b; }

extern "C" void kernel_launch(void* const* d_in, const int* in_sizes, int n_in,
                              void* d_out, int out_size) {
    static bool init = false;
    static float *p_h, *p_m, *p_agg, *p_gi, *p_gh, *p_pool, *p_cnt, *p_fc1, *p_scale, *p_shift;
    static __nv_bfloat16 *p_xs, *p_hs, *p_as, *p_Bproj, *p_Bggc, *p_Bwih, *p_Bwhh;
    if (!init) {
        cudaGetSymbolAddress((void**)&p_h, g_h);
        cudaGetSymbolAddress((void**)&p_m, g_m);
        cudaGetSymbolAddress((void**)&p_agg, g_agg);
        cudaGetSymbolAddress((void**)&p_gi, g_gi);
        cudaGetSymbolAddress((void**)&p_gh, g_gh);
        cudaGetSymbolAddress((void**)&p_pool, g_pool);
        cudaGetSymbolAddress((void**)&p_cnt, g_cnt);
        cudaGetSymbolAddress((void**)&p_fc1, g_fc1);
        cudaGetSymbolAddress((void**)&p_scale, g_scale);
        cudaGetSymbolAddress((void**)&p_shift, g_shift);
        cudaGetSymbolAddress((void**)&p_xs, g_xs);
        cudaGetSymbolAddress((void**)&p_hs, g_hs);
        cudaGetSymbolAddress((void**)&p_as, g_as);
        cudaGetSymbolAddress((void**)&p_Bproj, g_Bproj);
        cudaGetSymbolAddress((void**)&p_Bggc, g_Bggc);
        cudaGetSymbolAddress((void**)&p_Bwih, g_Bwih);
        cudaGetSymbolAddress((void**)&p_Bwhh, g_Bwhh);
        init = true;
    }

    const float *x, *projW, *projb;
    const void  *edge, *batch;
    const float *bn1g, *bn1b, *bn1m, *bn1v;
    const float *bn2g, *bn2b, *bn2m, *bn2v;
    const float *bnfg, *bnfb, *bnfm, *bnfv;
    const float *ggcW, *wih, *whh, *bih, *bhh, *fc1W, *fc1b, *fc2W, *fc2b;

    x     = (const float*)d_in[0];
    edge  = d_in[1];
    batch = d_in[2];
    projW = (const float*)d_in[3];
    projb = (const float*)d_in[4];
    bn1g = (const float*)d_in[5]; bn1b = (const float*)d_in[6];
    bn1m = (const float*)d_in[7]; bn1v = (const float*)d_in[8];

    if (in_sizes[9] == 120000) {
        ggcW = (const float*)d_in[9];
        wih  = (const float*)d_in[10]; whh = (const float*)d_in[11];
        bih  = (const float*)d_in[12]; bhh = (const float*)d_in[13];
        bn2g = (const float*)d_in[14]; bn2b = (const float*)d_in[15];
        bn2m = (const float*)d_in[16]; bn2v = (const float*)d_in[17];
        fc1W = (const float*)d_in[18]; fc1b = (const float*)d_in[19];
        bnfg = (const float*)d_in[20]; bnfb = (const float*)d_in[21];
        bnfm = (const float*)d_in[22]; bnfv = (const float*)d_in[23];
        fc2W = (const float*)d_in[24]; fc2b = (const float*)d_in[25];
    } else {
        bn2g = (const float*)d_in[9];  bn2b = (const float*)d_in[10];
        bn2m = (const float*)d_in[11]; bn2v = (const float*)d_in[12];
        bnfg = (const float*)d_in[13]; bnfb = (const float*)d_in[14];
        bnfm = (const float*)d_in[15]; bnfv = (const float*)d_in[16];
        ggcW = (const float*)d_in[17];
        wih  = (const float*)d_in[18]; whh = (const float*)d_in[19];
        bih  = (const float*)d_in[20]; bhh = (const float*)d_in[21];
        fc1W = (const float*)d_in[22]; fc1b = (const float*)d_in[23];
        fc2W = (const float*)d_in[24]; fc2b = (const float*)d_in[25];
    }

    const int T = 256;

    k_detect<<<1, 32>>>((const int*)edge, (const int*)batch);
    k_conv_edges<<<cdiv(2 * NE, T), T>>>(edge);
    k_conv_batch<<<cdiv(NN, T), T>>>(batch);

    k_bnprep<<<1, 256>>>(bn1g, bn1b, bn1m, bn1v, 0);
    k_bnprep<<<1, 256>>>(bn2g, bn2b, bn2m, bn2v, 1);
    k_bnprep<<<1, 256>>>(bnfg, bnfb, bnfm, bnfv, 2);

    // weight splits (small)
    k_splitB<<<cdiv(256 * NCH, T), T>>>(projW, p_Bproj, HID, 256, INDIM, 1);
    for (int i = 0; i < 3; i++)
        k_splitB<<<cdiv(256 * NCH, T), T>>>(ggcW + (size_t)i * HID * HID,
                                            p_Bggc + (size_t)i * 256 * K3, HID, 256, HID, 0);
    k_splitB<<<cdiv(640 * NCH, T), T>>>(wih, p_Bwih, H3, 640, HID, 1);
    k_splitB<<<cdiv(640 * NCH, T), T>>>(whh, p_Bwhh, H3, 640, HID, 1);

    const int MT = cdiv(NN, 128);  // 782

    // h = relu(bn1(x @ projW^T + projb))
    k_splitA<<<cdiv(NN * NCH, T), T>>>(x, p_xs, INDIM);
    k_tgemm<<<dim3(4, MT), 256>>>(p_xs, p_Bproj, p_h, NN, HID,
                                  projb, p_scale, p_shift, 1);

    for (int it = 0; it < 3; it++) {
        k_splitA<<<cdiv(NN * NCH, T), T>>>(p_h, p_hs, HID);
        // m = h @ ggc_W[it]
        k_tgemm<<<dim3(4, MT), 256>>>(p_hs, p_Bggc + (size_t)it * 256 * K3,
                                      p_m, NN, HID, nullptr, nullptr, nullptr, 0);
        // agg
        k_zero<<<cdiv(NN * HID, T), T>>>(p_agg, NN * HID);
        k_scatter<<<cdiv(NE * 50, T), T>>>();
        k_splitA<<<cdiv(NN * NCH, T), T>>>(p_agg, p_as, HID);
        // gi = agg @ wih^T + bih ; gh = h @ whh^T + bhh
        k_tgemm<<<dim3(10, MT), 256>>>(p_as, p_Bwih, p_gi, NN, H3,
                                       bih, nullptr, nullptr, 0);
        k_tgemm<<<dim3(10, MT), 256>>>(p_hs, p_Bwhh, p_gh, NN, H3,
                                       bhh, nullptr, nullptr, 0);
        k_gru<<<cdiv(NN * HID, T), T>>>();
    }

    k_bn2relu<<<cdiv(NN * HID, T), T>>>();

    k_zero<<<cdiv(NG * 400, T), T>>>(p_pool, NG * 400);
    k_zero<<<cdiv(NG, T), T>>>(p_cnt, NG);
    k_pool<<<cdiv(NN * 50, T), T>>>();
    k_pool_fin<<<cdiv(NG * HID, T), T>>>();

    {
        dim3 grid(cdiv(HID, BN), cdiv(NG, BM));
        k_gemm<<<grid, T>>>(p_pool, fc1W, p_fc1, NG, HID, 2 * HID, 1,
                            fc1b, p_scale + 2 * HID, p_shift + 2 * HID, 1);
    }
    {
        dim3 grid(cdiv(2, BN), cdiv(NG, BM));
        k_gemm<<<grid, T>>>(p_fc1, fc2W, (float*)d_out, NG, 2, HID, 1,
                            fc2b, nullptr, nullptr, 0);
    }
}

// round 5
// speedup vs baseline: 1.7895x; 1.0709x over previous
#include <cuda_runtime.h>
#include <cuda_bf16.h>
#include <stdint.h>
#include <math.h>

#define NN    100000
#define NE    1600000
#define NG    512
#define HID   200
#define H3    600
#define INDIM 205

#define KP    208      // padded K per section
#define K3    624      // 3*KP
#define NCH   78       // K3/8 chunks
#define NSTEP 39       // K3/16

// ---------------- scratch (device globals; no runtime alloc) ----------------
__device__ float g_h  [(size_t)NN * HID];
__device__ float g_m  [(size_t)NN * HID];
__device__ float g_agg[(size_t)NN * HID];
__device__ float g_gi [(size_t)NN * H3];
__device__ float g_gh [(size_t)NN * H3];
__device__ float g_pool[NG * 2 * HID];
__device__ float g_cnt [NG];
__device__ float g_fc1 [NG * HID];
__device__ float g_scale[3 * HID];
__device__ float g_shift[3 * HID];
__device__ int   g_src[NE];
__device__ int   g_dst[NE];
__device__ int   g_batch[NN];
__device__ int   g_flag_e;
__device__ int   g_flag_b;

// bf16 split buffers
__device__ __nv_bfloat16 g_xs[(size_t)NN * K3];
__device__ __nv_bfloat16 g_hs[(size_t)NN * K3];
__device__ __nv_bfloat16 g_as[(size_t)NN * K3];
__device__ __nv_bfloat16 g_Bproj[256 * K3];
__device__ __nv_bfloat16 g_Bggc [3][256 * K3];
__device__ __nv_bfloat16 g_Bwih [640 * K3];
__device__ __nv_bfloat16 g_Bwhh [640 * K3];

// ---------------- dtype detection (int64 vs int32) ----------------
__global__ void k_detect(const int* __restrict__ ew, const int* __restrict__ bw) {
    if (blockIdx.x == 0 && threadIdx.x == 0) {
        int fe = 1;
        for (int w = 2 * NE - 255; w < 2 * NE; w += 2)
            if (ew[w] != 0) fe = 0;
        g_flag_e = fe;
        int fb = 1;
        for (int w = NN - 255; w < NN; w += 2)
            if (bw[w] != 0) fb = 0;
        g_flag_b = fb;
    }
}

__global__ void k_conv_edges(const void* __restrict__ e) {
    int i = blockIdx.x * blockDim.x + threadIdx.x;
    if (i >= 2 * NE) return;
    int v = g_flag_e ? (int)((const long long*)e)[i] : ((const int*)e)[i];
    if (i < NE) g_src[i] = v; else g_dst[i - NE] = v;
}

__global__ void k_conv_batch(const void* __restrict__ b) {
    int i = blockIdx.x * blockDim.x + threadIdx.x;
    if (i >= NN) return;
    g_batch[i] = g_flag_b ? (int)((const long long*)b)[i] : ((const int*)b)[i];
}

// ---------------- merged BN param prep (600 threads, 1 block) ---------------
__global__ void k_bnprep_all(
    const float* g1, const float* b1, const float* m1, const float* v1,
    const float* g2, const float* b2, const float* m2, const float* v2,
    const float* gf, const float* bf, const float* mf, const float* vf) {
    int j = threadIdx.x;
    if (j >= 3 * HID) return;
    int which = j / HID, jj = j - which * HID;
    const float *g, *b, *m, *v;
    if (which == 0)      { g = g1; b = b1; m = m1; v = v1; }
    else if (which == 1) { g = g2; b = b2; m = m2; v = v2; }
    else                 { g = gf; b = bf; m = mf; v = vf; }
    float s = g[jj] * rsqrtf(v[jj] + 1e-5f);
    g_scale[j] = s;
    g_shift[j] = b[jj] - m[jj] * s;
}

// ---------------- bf16 split of activations: [M,K] f32 -> [M,624] bf16 ------
// layout per row: [hi(0..207) | lo(0..207) | hi(0..207)], zeros for k >= K
__global__ void k_splitA(const float* __restrict__ in, __nv_bfloat16* __restrict__ out,
                         int K) {
    int idx = blockIdx.x * blockDim.x + threadIdx.x;
    if (idx >= NN * NCH) return;
    int m = idx / NCH, ch = idx - (idx / NCH) * NCH;
    int s = ch / 26;
    int k0 = (ch - s * 26) * 8;
    const float* src = in + (size_t)m * K + k0;
    __nv_bfloat16 o[8];
#pragma unroll
    for (int i = 0; i < 8; i++) {
        float v = (k0 + i < K) ? src[i] : 0.f;
        __nv_bfloat16 hi = __float2bfloat16(v);
        o[i] = (s == 1) ? __float2bfloat16(v - __bfloat162float(hi)) : hi;
    }
    *(uint4*)(out + (size_t)m * K3 + ch * 8) = *(const uint4*)o;
}

// ---------------- bf16 split of weights: logical B[K,N] -> out[Npad,624] ----
// out[n][s*208+k]: s0=hi, s1=hi, s2=lo.  trans=1: W is [N,K] row-major.
__global__ void k_splitB(const float* __restrict__ W, __nv_bfloat16* __restrict__ out,
                         int N, int Npad, int K, int trans) {
    int idx = blockIdx.x * blockDim.x + threadIdx.x;
    if (idx >= Npad * NCH) return;
    int n = idx / NCH, ch = idx - (idx / NCH) * NCH;
    int s = ch / 26;
    int k0 = (ch - s * 26) * 8;
    __nv_bfloat16 o[8];
#pragma unroll
    for (int i = 0; i < 8; i++) {
        int k = k0 + i;
        float v = 0.f;
        if (n < N && k < K) v = trans ? W[(size_t)n * K + k] : W[(size_t)k * N + n];
        __nv_bfloat16 hi = __float2bfloat16(v);
        o[i] = (s == 2) ? __float2bfloat16(v - __bfloat162float(hi)) : hi;
    }
    *(uint4*)(out + (size_t)n * K3 + ch * 8) = *(const uint4*)o;
}

// ---------------- tensor-core GEMM: C[M,N] = A'[M,624] @ B'[Npad,624]^T -----
// 128x64 CTA tile, 8 warps (4x2), warp tile 32x32, mma.m16n8k16.bf16
// 3-stage cp.async pipeline, one __syncthreads per k-step.
#define SA_STRIDE 24
#define SB_STRIDE 24
#define STAGES    3

__global__ void __launch_bounds__(256)
k_tgemm(const __nv_bfloat16* __restrict__ A, const __nv_bfloat16* __restrict__ B,
        float* __restrict__ C, int M, int N,
        const float* __restrict__ bias,
        const float* __restrict__ scale, const float* __restrict__ shift,
        int relu) {
    __shared__ __nv_bfloat16 sA[STAGES][128 * SA_STRIDE];
    __shared__ __nv_bfloat16 sB[STAGES][64 * SB_STRIDE];

    const int tid  = threadIdx.x;
    const int warp = tid >> 5, lane = tid & 31;
    const int wm = warp & 3, wn = warp >> 2;
    const int m0 = blockIdx.y * 128;
    const int n0 = blockIdx.x * 64;

    const int arow = tid >> 1;
    const int akc  = (tid & 1) * 8;

    float acc[2][4][4];
#pragma unroll
    for (int mi = 0; mi < 2; mi++)
#pragma unroll
        for (int ni = 0; ni < 4; ni++)
#pragma unroll
            for (int j = 0; j < 4; j++) acc[mi][ni][j] = 0.f;

    const size_t a_off = (size_t)(m0 + arow) * K3 + akc;
    const size_t b_off = (size_t)(n0 + arow) * K3 + akc;   // tid<128 only
    const int a_valid = (m0 + arow < M) ? 16 : 0;

    // stage issue helper (macro to keep asm simple)
#define ISSUE_STAGE(st, ks)                                                     \
    do {                                                                        \
        uint32_t d_ = (uint32_t)__cvta_generic_to_shared(                       \
            &sA[st][arow * SA_STRIDE + akc]);                                   \
        asm volatile("cp.async.cg.shared.global [%0], [%1], 16, %2;\n"          \
                     :: "r"(d_), "l"(A + a_off + (ks) * 16), "r"(a_valid));     \
        if (tid < 128) {                                                        \
            uint32_t db_ = (uint32_t)__cvta_generic_to_shared(                  \
                &sB[st][arow * SB_STRIDE + akc]);                               \
            asm volatile("cp.async.cg.shared.global [%0], [%1], 16, 16;\n"      \
                         :: "r"(db_), "l"(B + b_off + (ks) * 16));              \
        }                                                                       \
    } while (0)

    // prologue: stages 0 and 1, one commit group each
    ISSUE_STAGE(0, 0);
    asm volatile("cp.async.commit_group;\n");
    ISSUE_STAGE(1, 1);
    asm volatile("cp.async.commit_group;\n");

    const int lr  = lane & 15;
    const int lcb = (lane >> 4) * 8;
    const int bn  = lane >> 2;
    const int bk  = (lane & 3) * 2;

    for (int ks = 0; ks < NSTEP; ks++) {
        // stage ks ready when all but newest 1 group complete
        asm volatile("cp.async.wait_group 1;\n");
        __syncthreads();

        // issue stage ks+2 (buffer (ks+2)%3 == (ks-1)%3; all readers passed barrier)
        if (ks + 2 < NSTEP) {
            int st = (ks + 2) % STAGES;
            ISSUE_STAGE(st, ks + 2);
        }
        asm volatile("cp.async.commit_group;\n");   // empty group OK, keeps accounting

        const int buf = ks % STAGES;
        uint32_t a[2][4];
        uint32_t b[4][2];
#pragma unroll
        for (int mi = 0; mi < 2; mi++) {
            uint32_t addr = (uint32_t)__cvta_generic_to_shared(
                &sA[buf][(wm * 32 + mi * 16 + lr) * SA_STRIDE + lcb]);
            asm volatile("ldmatrix.sync.aligned.m8n8.x4.shared.b16 {%0,%1,%2,%3}, [%4];"
                         : "=r"(a[mi][0]), "=r"(a[mi][1]), "=r"(a[mi][2]), "=r"(a[mi][3])
                         : "r"(addr));
        }
#pragma unroll
        for (int ni = 0; ni < 4; ni++) {
            const __nv_bfloat16* p = &sB[buf][(wn * 32 + ni * 8 + bn) * SB_STRIDE + bk];
            b[ni][0] = *(const uint32_t*)p;
            b[ni][1] = *(const uint32_t*)(p + 8);
        }
#pragma unroll
        for (int mi = 0; mi < 2; mi++)
#pragma unroll
            for (int ni = 0; ni < 4; ni++) {
                asm volatile(
                    "mma.sync.aligned.m16n8k16.row.col.f32.bf16.bf16.f32 "
                    "{%0,%1,%2,%3}, {%4,%5,%6,%7}, {%8,%9}, {%0,%1,%2,%3};"
                    : "+f"(acc[mi][ni][0]), "+f"(acc[mi][ni][1]),
                      "+f"(acc[mi][ni][2]), "+f"(acc[mi][ni][3])
                    : "r"(a[mi][0]), "r"(a[mi][1]), "r"(a[mi][2]), "r"(a[mi][3]),
                      "r"(b[ni][0]), "r"(b[ni][1]));
            }
    }
#undef ISSUE_STAGE

    // epilogue
    const int r = lane >> 2;
    const int c = (lane & 3) * 2;
#pragma unroll
    for (int mi = 0; mi < 2; mi++) {
#pragma unroll
        for (int ni = 0; ni < 4; ni++) {
            int n = n0 + wn * 32 + ni * 8 + c;
            if (n >= N) continue;
            float bia0 = 0.f, bia1 = 0.f, sc0 = 1.f, sc1 = 1.f, sh0 = 0.f, sh1 = 0.f;
            bool n1ok = (n + 1 < N);
            if (bias)  { bia0 = bias[n]; if (n1ok) bia1 = bias[n + 1]; }
            if (scale) { sc0 = scale[n]; sh0 = shift[n];
                         if (n1ok) { sc1 = scale[n + 1]; sh1 = shift[n + 1]; } }
#pragma unroll
            for (int half = 0; half < 2; half++) {
                int m = m0 + wm * 32 + mi * 16 + half * 8 + r;
                if (m >= M) continue;
                float v0 = acc[mi][ni][half * 2 + 0] + bia0;
                float v1 = acc[mi][ni][half * 2 + 1] + bia1;
                if (scale) { v0 = v0 * sc0 + sh0; v1 = v1 * sc1 + sh1; }
                if (relu)  { v0 = fmaxf(v0, 0.f); v1 = fmaxf(v1, 0.f); }
                float* p = C + (size_t)m * N + n;
                p[0] = v0;
                if (n1ok) p[1] = v1;
            }
        }
    }
}

// ---------------- small SIMT GEMM (kept for fc1/fc2) ------------------------
#define BM 64
#define BN 64
#define BK 16
__global__ void k_gemm(const float* __restrict__ A, const float* __restrict__ B,
                       float* __restrict__ C, int M, int N, int K, int transB,
                       const float* __restrict__ bias,
                       const float* __restrict__ scale,
                       const float* __restrict__ shift, int relu) {
    __shared__ float As[BK][BM];
    __shared__ float Bs[BK][BN + 4];
    const int m0 = blockIdx.y * BM;
    const int n0 = blockIdx.x * BN;
    const int tid = threadIdx.x;
    const int tm = tid >> 4;
    const int tn = tid & 15;
    float acc[4][4];
#pragma unroll
    for (int i = 0; i < 4; i++)
#pragma unroll
        for (int j = 0; j < 4; j++) acc[i][j] = 0.f;

    for (int k0 = 0; k0 < K; k0 += BK) {
        {
            int ar = tid >> 2;
            int ac = (tid & 3) * 4;
            int m = m0 + ar;
#pragma unroll
            for (int i = 0; i < 4; i++) {
                int k = k0 + ac + i;
                As[ac + i][ar] = (m < M && k < K) ? A[(size_t)m * K + k] : 0.f;
            }
        }
        if (!transB) {
            int br = tid >> 4;
            int bc = (tid & 15) * 4;
            int k = k0 + br;
#pragma unroll
            for (int i = 0; i < 4; i++) {
                int n = n0 + bc + i;
                Bs[br][bc + i] = (k < K && n < N) ? B[(size_t)k * N + n] : 0.f;
            }
        } else {
            int br = tid >> 2;
            int bc = (tid & 3) * 4;
            int n = n0 + br;
#pragma unroll
            for (int i = 0; i < 4; i++) {
                int k = k0 + bc + i;
                Bs[bc + i][br] = (n < N && k < K) ? B[(size_t)n * K + k] : 0.f;
            }
        }
        __syncthreads();
#pragma unroll
        for (int k = 0; k < BK; k++) {
            float a[4], b[4];
#pragma unroll
            for (int i = 0; i < 4; i++) a[i] = As[k][tm * 4 + i];
#pragma unroll
            for (int j = 0; j < 4; j++) b[j] = Bs[k][tn * 4 + j];
#pragma unroll
            for (int i = 0; i < 4; i++)
#pragma unroll
                for (int j = 0; j < 4; j++) acc[i][j] += a[i] * b[j];
        }
        __syncthreads();
    }
#pragma unroll
    for (int i = 0; i < 4; i++) {
        int m = m0 + tm * 4 + i;
        if (m >= M) continue;
#pragma unroll
        for (int j = 0; j < 4; j++) {
            int n = n0 + tn * 4 + j;
            if (n >= N) continue;
            float v = acc[i][j];
            if (bias)  v += bias[n];
            if (scale) v = v * scale[n] + shift[n];
            if (relu)  v = fmaxf(v, 0.f);
            C[(size_t)m * N + n] = v;
        }
    }
}

// ---------------- zero helper ----------------
__global__ void k_zero(float* __restrict__ p, int n) {
    int i = blockIdx.x * blockDim.x + threadIdx.x;
    if (i < n) p[i] = 0.f;
}

// ---------------- edge scatter-add ----------------
__global__ void k_scatter() {
    int t = blockIdx.x * blockDim.x + threadIdx.x;
    if (t >= NE * 50) return;
    int e = t / 50;
    int c = t - e * 50;
    int s = g_src[e];
    int d = g_dst[e];
    const float4 v = *reinterpret_cast<const float4*>(&g_m[(size_t)s * HID + c * 4]);
    float* p = &g_agg[(size_t)d * HID + c * 4];
    asm volatile("red.global.add.v4.f32 [%0], {%1,%2,%3,%4};"
                 :: "l"(p), "f"(v.x), "f"(v.y), "f"(v.z), "f"(v.w) : "memory");
}

// ---------------- GRU cell (vec4) + fused bf16 split write ------------------
__device__ __forceinline__ float sigm(float x) { return 1.f / (1.f + expf(-x)); }

__global__ void k_gru(int write_split) {
    int t = blockIdx.x * blockDim.x + threadIdx.x;
    if (t >= NN * 50) return;
    int n = t / 50, q = t - n * 50;
    int j = q * 4;
    const float* gi = g_gi + (size_t)n * H3;
    const float* gh = g_gh + (size_t)n * H3;
    float4 ir4 = *(const float4*)(gi + j);
    float4 iz4 = *(const float4*)(gi + j + 200);
    float4 in4 = *(const float4*)(gi + j + 400);
    float4 hr4 = *(const float4*)(gh + j);
    float4 hz4 = *(const float4*)(gh + j + 200);
    float4 hn4 = *(const float4*)(gh + j + 400);
    float* hp = g_h + (size_t)n * HID + j;
    float4 h4 = *(float4*)hp;

    float hv[4];
    {
        const float ir[4] = {ir4.x, ir4.y, ir4.z, ir4.w};
        const float iz[4] = {iz4.x, iz4.y, iz4.z, iz4.w};
        const float in_[4] = {in4.x, in4.y, in4.z, in4.w};
        const float hr[4] = {hr4.x, hr4.y, hr4.z, hr4.w};
        const float hz[4] = {hz4.x, hz4.y, hz4.z, hz4.w};
        const float hn[4] = {hn4.x, hn4.y, hn4.z, hn4.w};
        const float ho[4] = {h4.x, h4.y, h4.z, h4.w};
#pragma unroll
        for (int i = 0; i < 4; i++) {
            float r = sigm(ir[i] + hr[i]);
            float z = sigm(iz[i] + hz[i]);
            float nn = tanhf(in_[i] + r * hn[i]);
            hv[i] = (1.f - z) * nn + z * ho[i];
        }
    }
    *(float4*)hp = make_float4(hv[0], hv[1], hv[2], hv[3]);

    if (write_split) {
        __nv_bfloat16 hi[4], lo[4];
#pragma unroll
        for (int i = 0; i < 4; i++) {
            hi[i] = __float2bfloat16(hv[i]);
            lo[i] = __float2bfloat16(hv[i] - __bfloat162float(hi[i]));
        }
        __nv_bfloat16* o = g_hs + (size_t)n * K3 + j;   // j multiple of 4 -> 8B-aligned? 4*2=8B aligned
        // hi section at +0, lo at +208, hi at +416 (all even element offsets -> 4B aligned)
        ((uint32_t*)o)[0] = *(const uint32_t*)&hi[0];
        ((uint32_t*)o)[1] = *(const uint32_t*)&hi[2];
        ((uint32_t*)(o + 208))[0] = *(const uint32_t*)&lo[0];
        ((uint32_t*)(o + 208))[1] = *(const uint32_t*)&lo[2];
        ((uint32_t*)(o + 416))[0] = *(const uint32_t*)&hi[0];
        ((uint32_t*)(o + 416))[1] = *(const uint32_t*)&hi[2];
    }
}

__global__ void k_bn2relu() {
    int idx = blockIdx.x * blockDim.x + threadIdx.x;
    if (idx >= NN * HID) return;
    int j = idx % HID;
    g_h[idx] = fmaxf(g_h[idx] * g_scale[HID + j] + g_shift[HID + j], 0.f);
}

// ---------------- pooling ----------------
__global__ void k_pool() {
    int t = blockIdx.x * blockDim.x + threadIdx.x;
    if (t >= NN * 50) return;
    int node = t / 50;
    int c = t - node * 50;
    int b = g_batch[node];
    const float4 v = *reinterpret_cast<const float4*>(&g_h[(size_t)node * HID + c * 4]);
    float* mp = &g_pool[b * 400 + c * 4];
    atomicAdd(mp + 0, v.x); atomicAdd(mp + 1, v.y);
    atomicAdd(mp + 2, v.z); atomicAdd(mp + 3, v.w);
    int* xp = (int*)&g_pool[b * 400 + 200 + c * 4];
    atomicMax(xp + 0, __float_as_int(v.x));
    atomicMax(xp + 1, __float_as_int(v.y));
    atomicMax(xp + 2, __float_as_int(v.z));
    atomicMax(xp + 3, __float_as_int(v.w));
    if (c == 0) atomicAdd(&g_cnt[b], 1.0f);
}

__global__ void k_pool_fin() {
    int idx = blockIdx.x * blockDim.x + threadIdx.x;
    if (idx >= NG * HID) return;
    int g = idx / HID;
    int j = idx - g * HID;
    g_pool[g * 400 + j] *= 1.f / fmaxf(g_cnt[g], 1.f);
}

// ---------------- host launch ----------------
static inline int cdiv(int a, int b) { return (a + b - 1) / b; }

extern "C" void kernel_launch(void* const* d_in, const int* in_sizes, int n_in,
                              void* d_out, int out_size) {
    static bool init = false;
    static float *p_h, *p_m, *p_agg, *p_gi, *p_gh, *p_pool, *p_cnt, *p_fc1, *p_scale, *p_shift;
    static __nv_bfloat16 *p_xs, *p_hs, *p_as, *p_Bproj, *p_Bggc, *p_Bwih, *p_Bwhh;
    if (!init) {
        cudaGetSymbolAddress((void**)&p_h, g_h);
        cudaGetSymbolAddress((void**)&p_m, g_m);
        cudaGetSymbolAddress((void**)&p_agg, g_agg);
        cudaGetSymbolAddress((void**)&p_gi, g_gi);
        cudaGetSymbolAddress((void**)&p_gh, g_gh);
        cudaGetSymbolAddress((void**)&p_pool, g_pool);
        cudaGetSymbolAddress((void**)&p_cnt, g_cnt);
        cudaGetSymbolAddress((void**)&p_fc1, g_fc1);
        cudaGetSymbolAddress((void**)&p_scale, g_scale);
        cudaGetSymbolAddress((void**)&p_shift, g_shift);
        cudaGetSymbolAddress((void**)&p_xs, g_xs);
        cudaGetSymbolAddress((void**)&p_hs, g_hs);
        cudaGetSymbolAddress((void**)&p_as, g_as);
        cudaGetSymbolAddress((void**)&p_Bproj, g_Bproj);
        cudaGetSymbolAddress((void**)&p_Bggc, g_Bggc);
        cudaGetSymbolAddress((void**)&p_Bwih, g_Bwih);
        cudaGetSymbolAddress((void**)&p_Bwhh, g_Bwhh);
        init = true;
    }

    const float *x, *projW, *projb;
    const void  *edge, *batch;
    const float *bn1g, *bn1b, *bn1m, *bn1v;
    const float *bn2g, *bn2b, *bn2m, *bn2v;
    const float *bnfg, *bnfb, *bnfm, *bnfv;
    const float *ggcW, *wih, *whh, *bih, *bhh, *fc1W, *fc1b, *fc2W, *fc2b;

    x     = (const float*)d_in[0];
    edge  = d_in[1];
    batch = d_in[2];
    projW = (const float*)d_in[3];
    projb = (const float*)d_in[4];
    bn1g = (const float*)d_in[5]; bn1b = (const float*)d_in[6];
    bn1m = (const float*)d_in[7]; bn1v = (const float*)d_in[8];

    if (in_sizes[9] == 120000) {
        ggcW = (const float*)d_in[9];
        wih  = (const float*)d_in[10]; whh = (const float*)d_in[11];
        bih  = (const float*)d_in[12]; bhh = (const float*)d_in[13];
        bn2g = (const float*)d_in[14]; bn2b = (const float*)d_in[15];
        bn2m = (const float*)d_in[16]; bn2v = (const float*)d_in[17];
        fc1W = (const float*)d_in[18]; fc1b = (const float*)d_in[19];
        bnfg = (const float*)d_in[20]; bnfb = (const float*)d_in[21];
        bnfm = (const float*)d_in[22]; bnfv = (const float*)d_in[23];
        fc2W = (const float*)d_in[24]; fc2b = (const float*)d_in[25];
    } else {
        bn2g = (const float*)d_in[9];  bn2b = (const float*)d_in[10];
        bn2m = (const float*)d_in[11]; bn2v = (const float*)d_in[12];
        bnfg = (const float*)d_in[13]; bnfb = (const float*)d_in[14];
        bnfm = (const float*)d_in[15]; bnfv = (const float*)d_in[16];
        ggcW = (const float*)d_in[17];
        wih  = (const float*)d_in[18]; whh = (const float*)d_in[19];
        bih  = (const float*)d_in[20]; bhh = (const float*)d_in[21];
        fc1W = (const float*)d_in[22]; fc1b = (const float*)d_in[23];
        fc2W = (const float*)d_in[24]; fc2b = (const float*)d_in[25];
    }

    const int T = 256;
    const int MT = cdiv(NN, 128);  // 782

    // ---- launch order chosen so ncu (-s 5 -c 1) profiles k_tgemm(proj) ----
    k_splitB<<<cdiv(256 * NCH, T), T>>>(projW, p_Bproj, HID, 256, INDIM, 1);   // 0
    k_bnprep_all<<<1, 640>>>(bn1g, bn1b, bn1m, bn1v,
                             bn2g, bn2b, bn2m, bn2v,
                             bnfg, bnfb, bnfm, bnfv);                           // 1
    k_splitA<<<cdiv(NN * NCH, T), T>>>(x, p_xs, INDIM);                         // 2
    k_detect<<<1, 32>>>((const int*)edge, (const int*)batch);                   // 3
    k_conv_edges<<<cdiv(2 * NE, T), T>>>(edge);                                 // 4
    // h = relu(bn1(x @ projW^T + projb))
    k_tgemm<<<dim3(4, MT), 256>>>(p_xs, p_Bproj, p_h, NN, HID,
                                  projb, p_scale, p_shift, 1);                  // 5 <- profiled

    k_conv_batch<<<cdiv(NN, T), T>>>(batch);
    for (int i = 0; i < 3; i++)
        k_splitB<<<cdiv(256 * NCH, T), T>>>(ggcW + (size_t)i * HID * HID,
                                            p_Bggc + (size_t)i * 256 * K3, HID, 256, HID, 0);
    k_splitB<<<cdiv(640 * NCH, T), T>>>(wih, p_Bwih, H3, 640, HID, 1);
    k_splitB<<<cdiv(640 * NCH, T), T>>>(whh, p_Bwhh, H3, 640, HID, 1);

    // split of initial h
    k_splitA<<<cdiv(NN * NCH, T), T>>>(p_h, p_hs, HID);

    for (int it = 0; it < 3; it++) {
        // m = h @ ggc_W[it]
        k_tgemm<<<dim3(4, MT), 256>>>(p_hs, p_Bggc + (size_t)it * 256 * K3,
                                      p_m, NN, HID, nullptr, nullptr, nullptr, 0);
        // agg = scatter_add(m[src] -> dst)
        k_zero<<<cdiv(NN * HID, T), T>>>(p_agg, NN * HID);
        k_scatter<<<cdiv(NE * 50, T), T>>>();
        k_splitA<<<cdiv(NN * NCH, T), T>>>(p_agg, p_as, HID);
        // gi = agg @ wih^T + bih ; gh = h @ whh^T + bhh
        k_tgemm<<<dim3(10, MT), 256>>>(p_as, p_Bwih, p_gi, NN, H3,
                                       bih, nullptr, nullptr, 0);
        k_tgemm<<<dim3(10, MT), 256>>>(p_hs, p_Bwhh, p_gh, NN, H3,
                                       bhh, nullptr, nullptr, 0);
        // h = GRU(...) ; write bf16 split for next iteration (not needed after last)
        k_gru<<<cdiv(NN * 50, T), T>>>(it < 2 ? 1 : 0);
    }

    k_bn2relu<<<cdiv(NN * HID, T), T>>>();

    k_zero<<<cdiv(NG * 400, T), T>>>(p_pool, NG * 400);
    k_zero<<<cdiv(NG, T), T>>>(p_cnt, NG);
    k_pool<<<cdiv(NN * 50, T), T>>>();
    k_pool_fin<<<cdiv(NG * HID, T), T>>>();

    {
        dim3 grid(cdiv(HID, BN), cdiv(NG, BM));
        k_gemm<<<grid, T>>>(p_pool, fc1W, p_fc1, NG, HID, 2 * HID, 1,
                            fc1b, p_scale + 2 * HID, p_shift + 2 * HID, 1);
    }
    {
        dim3 grid(cdiv(2, BN), cdiv(NG, BM));
        k_gemm<<<grid, T>>>(p_fc1, fc2W, (float*)d_out, NG, 2, HID, 1,
                            fc2b, nullptr, nullptr, 0);
    }
}